// round 8
// baseline (speedup 1.0000x reference)
#include <cuda_runtime.h>
#include <cstdint>

// Conv2d VALID: x[32,64,112,112] f32, w[128,64,3,3] f32 -> out[32,128,110,110] f32
// Implicit GEMM, mma.sync.m16n8k8 tf32.
// Round 8: CTA 128m x 256n (4 oh rows x 64 ow), 8 warps (2m x 4n) of 64x64.
// Input window (32ch x 6 rows x 66 cols) staged once per ci-half as tf32
// float2 (k,k+4) pairs; A chunks double-buffered with float4-friendly perm.

namespace {

constexpr int CIN = 64, COUT = 128, H = 112, W = 112, OH = 110, OW = 110;
constexpr int A_STRIDE = 36;               // floats per A row (32 + 4 pad)
constexpr int SM_A_FLOATS = 128 * A_STRIDE;
constexpr int XS_KP = 18;                  // float2 per (row,col): 16 + 2 pad
constexpr int XS_F2 = 6 * 66 * XS_KP;      // 7128 float2
constexpr int SM_TOTAL = (2 * SM_A_FLOATS + 2 * XS_F2) * 4;   // 93888 B

__device__ float g_A_pre[18 * 4096];  // [kc][co 128][perm col 32] tf32

__device__ __forceinline__ float to_tf32(float v) {
    float o;
    asm("cvt.rna.tf32.f32 %0, %1;" : "=f"(o) : "f"(v));
    return o;
}

// perm col = q*8 + g*2 + e  <->  k = g*8 + q + 4*e
__global__ void prep_weights(const float* __restrict__ w) {
    int idx = blockIdx.x * 256 + threadIdx.x;  // 0 .. 73727
    int kc  = idx >> 12;
    int rem = idx & 4095;
    int co  = rem >> 5;
    int col = rem & 31;
    int q = col >> 3, r2 = col & 7, g = r2 >> 1, e = r2 & 1;
    int k  = g * 8 + q + 4 * e;
    int hh = kc / 9;
    int rs = kc - hh * 9;
    int ci = hh * 32 + k;
    g_A_pre[idx] = to_tf32(w[((size_t)co * CIN + ci) * 9 + rs]);
}

__global__ __launch_bounds__(256)
void conv_mma(const float* __restrict__ x, float* __restrict__ out)
{
    extern __shared__ float sm[];
    float*  Abuf[2] = { sm, sm + SM_A_FLOATS };
    float2* Xs      = (float2*)(sm + 2 * SM_A_FLOATS);

    const int tid  = threadIdx.x;
    const int wid  = tid >> 5;
    const int lane = tid & 31;
    const int wm   = wid >> 2;        // 0..1 (m half)
    const int wn   = wid & 3;         // 0..3 = output sub-row
    const int lr   = lane >> 2;       // 0..7
    const int lq   = lane & 3;        // 0..3

    const int ow0 = blockIdx.x * 64;
    const int oh0 = blockIdx.y * 4;
    const int bb  = blockIdx.z;

    float acc[4][8][4];
#pragma unroll
    for (int i = 0; i < 4; i++)
#pragma unroll
        for (int j = 0; j < 8; j++)
#pragma unroll
            for (int k = 0; k < 4; k++) acc[i][j][k] = 0.0f;

    const float* xb = x + (size_t)bb * CIN * H * W;

    // preload A chunk 0
    {
        const float4* src = (const float4*)g_A_pre;
#pragma unroll
        for (int i = 0; i < 4; ++i) {
            int idx = tid + 256 * i;
            float4 v = src[idx];
            *(float4*)(Abuf[0] + (idx >> 3) * A_STRIDE + (idx & 7) * 4) = v;
        }
    }

    for (int hh = 0; hh < 2; ++hh) {
        __syncthreads();   // prior compute done before Xs overwrite

        // ---- stage input window as tf32 (k,k+4) float2 pairs ----
        // flat = (kp*6 + row)*66 + col, col fastest -> coalesced LDG
#pragma unroll
        for (int i = 0; i < 25; ++i) {
            int flat = tid + 256 * i;
            if (flat < 16 * 6 * 66) {
                int col = flat % 66;
                int t2  = flat / 66;          // 0..95
                int row = t2 % 6;
                int kp  = t2 / 6;             // q*4 + g
                int q   = kp >> 2;
                int g   = kp & 3;
                int ch  = hh * 32 + g * 8 + q;
                int ih  = oh0 + row;
                int iw  = ow0 + col;
                float v0 = 0.0f, v1 = 0.0f;
                if (ih < H && iw < W) {
                    const float* p = xb + ((size_t)ch * H + ih) * W + iw;
                    v0 = to_tf32(p[0]);
                    v1 = to_tf32(p[4 * H * W]);
                }
                Xs[(row * 66 + col) * XS_KP + kp] = make_float2(v0, v1);
            }
        }
        __syncthreads();

        for (int t = 0; t < 9; ++t) {
            const int kc = hh * 9 + t;
            const int r  = t / 3;
            const int s  = t - r * 3;

            if (t > 0) __syncthreads();   // prev compute done before buffer overwrite

            // ---- prefetch next A chunk ----
            if (kc < 17) {
                const float4* src = (const float4*)(g_A_pre + (kc + 1) * 4096);
                float* dst = Abuf[(kc + 1) & 1];
#pragma unroll
                for (int i = 0; i < 4; ++i) {
                    int idx = tid + 256 * i;
                    float4 v = src[idx];
                    *(float4*)(dst + (idx >> 3) * A_STRIDE + (idx & 7) * 4) = v;
                }
            }

            const float*  Ab = Abuf[kc & 1];
            // B window base for this warp/tap
            const float2* xw = Xs + ((wn + r) * 66 + s) * XS_KP + lq * 4;

#pragma unroll
            for (int gp = 0; gp < 2; ++gp) {
                // A frags: 4 mf x 2 LDS.128 covering g = 2gp, 2gp+1
                uint32_t a[4][2][4];
#pragma unroll
                for (int mf = 0; mf < 4; ++mf) {
                    int row = wm * 64 + mf * 16 + lr;
                    float4 u0 = *(const float4*)(Ab + row * A_STRIDE + lq * 8 + gp * 4);
                    float4 u1 = *(const float4*)(Ab + (row + 8) * A_STRIDE + lq * 8 + gp * 4);
                    a[mf][0][0] = __float_as_uint(u0.x);
                    a[mf][0][1] = __float_as_uint(u1.x);
                    a[mf][0][2] = __float_as_uint(u0.y);
                    a[mf][0][3] = __float_as_uint(u1.y);
                    a[mf][1][0] = __float_as_uint(u0.z);
                    a[mf][1][1] = __float_as_uint(u1.z);
                    a[mf][1][2] = __float_as_uint(u0.w);
                    a[mf][1][3] = __float_as_uint(u1.w);
                }
                // B frags: 8 nf x 1 LDS.128 covering g = 2gp, 2gp+1
                uint32_t b[8][2][2];
#pragma unroll
                for (int nf = 0; nf < 8; ++nf) {
                    float4 v = *(const float4*)(xw + (nf * 8 + lr) * XS_KP + gp * 2);
                    b[nf][0][0] = __float_as_uint(v.x);
                    b[nf][0][1] = __float_as_uint(v.y);
                    b[nf][1][0] = __float_as_uint(v.z);
                    b[nf][1][1] = __float_as_uint(v.w);
                }
#pragma unroll
                for (int mf = 0; mf < 4; ++mf)
#pragma unroll
                    for (int nf = 0; nf < 8; ++nf)
#pragma unroll
                        for (int gs = 0; gs < 2; ++gs) {
                            asm volatile(
                                "mma.sync.aligned.m16n8k8.row.col.f32.tf32.tf32.f32 "
                                "{%0,%1,%2,%3}, {%4,%5,%6,%7}, {%8,%9}, {%0,%1,%2,%3};"
                                : "+f"(acc[mf][nf][0]), "+f"(acc[mf][nf][1]),
                                  "+f"(acc[mf][nf][2]), "+f"(acc[mf][nf][3])
                                : "r"(a[mf][gs][0]), "r"(a[mf][gs][1]),
                                  "r"(a[mf][gs][2]), "r"(a[mf][gs][3]),
                                  "r"(b[nf][gs][0]), "r"(b[nf][gs][1]));
                        }
            }
        }
    }

    // ---- epilogue: each warp owns one output row ----
    const int oh = oh0 + wn;
    if (oh < OH) {
#pragma unroll
        for (int mf = 0; mf < 4; ++mf) {
#pragma unroll
            for (int nf = 0; nf < 8; ++nf) {
                int ow = ow0 + nf * 8 + lq * 2;   // even
                if (ow < OW) {
                    int co0 = wm * 64 + mf * 16 + lr;
                    float* p0 = out + (((size_t)bb * COUT + co0) * OH + oh) * OW + ow;
                    *(float2*)p0 = make_float2(acc[mf][nf][0], acc[mf][nf][1]);
                    float* p1 = p0 + (size_t)8 * OH * OW;
                    *(float2*)p1 = make_float2(acc[mf][nf][2], acc[mf][nf][3]);
                }
            }
        }
    }
}

} // namespace

extern "C" void kernel_launch(void* const* d_in, const int* in_sizes, int n_in,
                              void* d_out, int out_size)
{
    const float* x = (const float*)d_in[0];
    const float* w = (const float*)d_in[1];
    float* out = (float*)d_out;

    cudaFuncSetAttribute(conv_mma, cudaFuncAttributeMaxDynamicSharedMemorySize, SM_TOTAL);

    prep_weights<<<18 * 4096 / 256, 256>>>(w);

    dim3 grid(2, 28, 32);   // ow tiles (2x64), oh tiles (28x4 covers 110), batch
    conv_mma<<<grid, 256, SM_TOTAL>>>(x, out);
}